// round 7
// baseline (speedup 1.0000x reference)
#include <cuda_runtime.h>
#include <cstdint>

#define N_NODES 40000
#define N_EDGES 640000
#define DIM 128
#define KC 32            // K chunk staged in smem
#define AST 68           // As row stride (words): 64 + 4 pad
#define WST 132          // Ws row stride (words): 128 + 4 pad

// Scratch (no cudaMalloc allowed)
__device__ float g_agg[N_NODES * DIM];
__device__ float g_h[N_NODES * DIM];
__device__ float g_colsum[DIM];
__device__ float g_colsumsq[DIM];

// ---------------- packed f32x2 helpers (PTX ISA sm_100+ base) ----------------
__device__ __forceinline__ unsigned long long dup_f32x2(float a) {
    unsigned long long d;
    uint32_t u = __float_as_uint(a);
    asm("mov.b64 %0, {%1, %1};" : "=l"(d) : "r"(u));
    return d;
}
__device__ __forceinline__ void fma_f32x2(unsigned long long& acc,
                                          unsigned long long a,
                                          unsigned long long w) {
    asm("fma.rn.f32x2 %0, %1, %2, %0;" : "+l"(acc) : "l"(a), "l"(w));
}

// ---------------------------------------------------------------------------
// K0: zero g_agg + BN stat accumulators
// ---------------------------------------------------------------------------
__global__ void k0z() {
    const int total = N_NODES * DIM / 4;
    float4 z = {0.f, 0.f, 0.f, 0.f};
    for (int idx = blockIdx.x * blockDim.x + threadIdx.x; idx < total;
         idx += gridDim.x * blockDim.x)
        ((float4*)g_agg)[idx] = z;
    if (blockIdx.x == 0 && threadIdx.x < DIM) {
        g_colsum[threadIdx.x]   = 0.0f;
        g_colsumsq[threadIdx.x] = 0.0f;
    }
}

// ---------------------------------------------------------------------------
// K1: edge scatter — one warp per edge, red.global.add.v4.f32 (proven, at LTS floor)
// ---------------------------------------------------------------------------
__global__ void k1_scatter(const float* __restrict__ x,
                           const int* __restrict__ ei) {
    int warp = (blockIdx.x * blockDim.x + threadIdx.x) >> 5;
    int lane = threadIdx.x & 31;
    if (warp >= N_EDGES) return;
    int src = __ldg(&ei[warp]);
    int dst = __ldg(&ei[N_EDGES + warp]);
    float4 v = __ldg((const float4*)x + src * (DIM / 4) + lane);
    float* dp = g_agg + (size_t)dst * DIM + lane * 4;
    asm volatile("red.global.add.v4.f32 [%0], {%1, %2, %3, %4};"
                 :: "l"(dp), "f"(v.x), "f"(v.y), "f"(v.z), "f"(v.w)
                 : "memory");
}

// ---------------------------------------------------------------------------
// K2: h = ((1+eps)x + agg) @ W^T, fused per-column sum/sumsq for BN.
//     Bias omitted (cancels exactly inside BatchNorm).
//     Inner loop in packed fma.rn.f32x2: 16 FFMA2 replace 32 FFMA per k-step.
//     acc2[q][p]: q = row 0..3, p = col-pair {cl,cl+1},{cl+2,cl+3},
//                 {cl+16,cl+17},{cl+18,cl+19}. W pairs loaded from smem as b64.
// ---------------------------------------------------------------------------
__global__ void __launch_bounds__(256, 3)
k2_gemm(const float* __restrict__ x, const float* __restrict__ Wm,
        const float* __restrict__ gin_eps) {
    __shared__ float As[KC][AST];     // As[k][r]
    __shared__ float Ws[KC][WST];     // Ws[k][n]
    __shared__ float cs[DIM], cs2[DIM];

    const int tid  = threadIdx.x;
    const int row0 = blockIdx.x * 64;             // 625 * 64 == 40000 exactly
    const float ce = 1.0f + __ldg(gin_eps);

    const int wid  = tid >> 5, lane = tid & 31;
    const int wr   = wid & 1,  wc   = wid >> 1;   // warp 2x4
    const int lr   = lane & 7, lc   = lane >> 3;  // lane 8x4
    const int rl   = wr * 32 + lr * 4;            // 4 contiguous rows
    const int cl   = wc * 32 + lc * 4;            // cols cl..cl+3 and cl+16..cl+19

    if (tid < DIM) { cs[tid] = 0.0f; cs2[tid] = 0.0f; }

    unsigned long long acc2[4][4];
#pragma unroll
    for (int q = 0; q < 4; q++)
#pragma unroll
        for (int p = 0; p < 4; p++) acc2[q][p] = 0ull;

    for (int kc = 0; kc < DIM; kc += KC) {
        __syncthreads();
        // Stage Ws[k][n] <- W[n][kc+k]  (transpose, 128 n x 8 float4)
        for (int i = tid; i < 128 * 8; i += 256) {
            int n = i >> 3, kq = i & 7;
            float4 w = __ldg((const float4*)Wm + n * 32 + (kc >> 2) + kq);
            Ws[kq * 4 + 0][n] = w.x;
            Ws[kq * 4 + 1][n] = w.y;
            Ws[kq * 4 + 2][n] = w.z;
            Ws[kq * 4 + 3][n] = w.w;
        }
        // Stage As[k][r] <- (1+eps)*x + agg  (transpose, 64 r x 8 float4)
        for (int i = tid; i < 64 * 8; i += 256) {
            int r = i >> 3, kq = i & 7;
            size_t off = (size_t)(row0 + r) * 32 + (kc >> 2) + kq;
            float4 xv = __ldg((const float4*)x + off);
            float4 gv = *((const float4*)g_agg + off);
            As[kq * 4 + 0][r] = fmaf(ce, xv.x, gv.x);
            As[kq * 4 + 1][r] = fmaf(ce, xv.y, gv.y);
            As[kq * 4 + 2][r] = fmaf(ce, xv.z, gv.z);
            As[kq * 4 + 3][r] = fmaf(ce, xv.w, gv.w);
        }
        __syncthreads();

#pragma unroll
        for (int kk = 0; kk < KC; kk++) {
            float4 av = *(const float4*)&As[kk][rl];
            // w column pairs straight from smem as packed b64 (16B aligned)
            ulonglong2 wp0 = *(const ulonglong2*)&Ws[kk][cl];       // {c,c+1},{c+2,c+3}
            ulonglong2 wp1 = *(const ulonglong2*)&Ws[kk][cl + 16];  // {c+16,..},{c+18,..}
            unsigned long long ad[4] = {dup_f32x2(av.x), dup_f32x2(av.y),
                                        dup_f32x2(av.z), dup_f32x2(av.w)};
#pragma unroll
            for (int q = 0; q < 4; q++) {
                fma_f32x2(acc2[q][0], ad[q], wp0.x);
                fma_f32x2(acc2[q][1], ad[q], wp0.y);
                fma_f32x2(acc2[q][2], ad[q], wp1.x);
                fma_f32x2(acc2[q][3], ad[q], wp1.y);
            }
        }
    }

    // Epilogue: store h + accumulate per-column sum/sumsq
    float csum[8], csq[8];
#pragma unroll
    for (int c = 0; c < 8; c++) { csum[c] = 0.0f; csq[c] = 0.0f; }

#pragma unroll
    for (int q = 0; q < 4; q++) {
        int row = row0 + rl + q;
        const float* af = (const float*)&acc2[q][0];   // 8 floats: cols cl..cl+3, cl+16..cl+19
        float4 o0 = {af[0], af[1], af[2], af[3]};
        float4 o1 = {af[4], af[5], af[6], af[7]};
        *(float4*)&g_h[(size_t)row * DIM + cl]      = o0;
        *(float4*)&g_h[(size_t)row * DIM + cl + 16] = o1;
#pragma unroll
        for (int c = 0; c < 8; c++) {
            float v = af[c];
            csum[c] += v;
            csq[c]  += v * v;
        }
    }
#pragma unroll
    for (int c = 0; c < 4; c++) {
        atomicAdd(&cs[cl + c],       csum[c]);
        atomicAdd(&cs[cl + 16 + c],  csum[c + 4]);
        atomicAdd(&cs2[cl + c],      csq[c]);
        atomicAdd(&cs2[cl + 16 + c], csq[c + 4]);
    }
    __syncthreads();
    if (tid < DIM) {
        atomicAdd(&g_colsum[tid],   cs[tid]);
        atomicAdd(&g_colsumsq[tid], cs2[tid]);
    }
}

// ---------------------------------------------------------------------------
// K3: out = relu(gamma*(h-mean)*rsqrt(var+eps)+beta) + x
// ---------------------------------------------------------------------------
__global__ void k3_final(const float* __restrict__ x,
                         const float* __restrict__ gamma,
                         const float* __restrict__ beta,
                         float* __restrict__ out) {
    __shared__ float sc_s[DIM], sh_s[DIM];
    if (threadIdx.x < DIM) {
        int c = threadIdx.x;
        const float invN = 1.0f / (float)N_NODES;
        float mean = g_colsum[c] * invN;
        float var  = g_colsumsq[c] * invN - mean * mean;
        float inv  = rsqrtf(var + 1e-5f);
        float sc   = __ldg(&gamma[c]) * inv;
        sc_s[c] = sc;
        sh_s[c] = __ldg(&beta[c]) - mean * sc;
    }
    __syncthreads();
    const int total = N_NODES * DIM / 4;
    for (int idx = blockIdx.x * blockDim.x + threadIdx.x; idx < total;
         idx += gridDim.x * blockDim.x) {
        int c4 = (idx & 31) << 2;
        float4 h  = ((const float4*)g_h)[idx];
        float4 xv = __ldg((const float4*)x + idx);
        float4 sc = *(float4*)&sc_s[c4];
        float4 sh = *(float4*)&sh_s[c4];
        float4 o;
        o.x = fmaxf(fmaf(h.x, sc.x, sh.x), 0.0f) + xv.x;
        o.y = fmaxf(fmaf(h.y, sc.y, sh.y), 0.0f) + xv.y;
        o.z = fmaxf(fmaf(h.z, sc.z, sh.z), 0.0f) + xv.z;
        o.w = fmaxf(fmaf(h.w, sc.w, sh.w), 0.0f) + xv.w;
        ((float4*)out)[idx] = o;
    }
}

// ---------------------------------------------------------------------------
extern "C" void kernel_launch(void* const* d_in, const int* in_sizes, int n_in,
                              void* d_out, int out_size) {
    const float* x       = (const float*)d_in[0];
    const int*   ei      = (const int*)d_in[1];
    const float* Wm      = (const float*)d_in[2];
    // d_in[3] = bias: cancels exactly inside BatchNorm -> unused
    const float* gamma   = (const float*)d_in[4];
    const float* beta    = (const float*)d_in[5];
    const float* gin_eps = (const float*)d_in[6];
    float* out = (float*)d_out;

    k0z<<<1184, 256>>>();
    k1_scatter<<<N_EDGES / 8, 256>>>(x, ei);      // 1 warp per edge
    k2_gemm<<<N_NODES / 64, 256>>>(x, Wm, gin_eps);
    k3_final<<<1184, 256>>>(x, gamma, beta, out);
}